// round 7
// baseline (speedup 1.0000x reference)
#include <cuda_runtime.h>

#define D 128
#define MAXN 40000
#define MAXE 640000

// ---------------- scratch (static device globals; no allocation) -------------
__device__ float g_deg[MAXN];
__device__ float g_dinv[MAXN];
__device__ int   g_cnt[MAXN];
__device__ int   g_offs[MAXN + 1];
__device__ int   g_cursor[MAXN];
__device__ int   g_srcs[MAXE];
__device__ float g_nrm[MAXE];
__device__ __align__(16) float g_H[MAXN * D];   // h = X @ W (current layer)
__device__ __align__(16) float g_G[MAXN * D];   // post-agg activations
__device__ int   g_is64;                        // edge_index dtype flag

// ---------------- dtype detection ---------------------------------------------
// Reads the first 1024 values as int64 (8KB -- safe under either dtype).
// int32 data reinterpreted as int64 combines random pairs -> values >= 2^32,
// out of [0, MAXN) with overwhelming probability. All-in-range => true int64.
__global__ void k_detect(const void* __restrict__ ei) {
    const long long* p = (const long long*)ei;
    bool bad = false;
    for (int j = threadIdx.x; j < 1024; j += 256) {
        long long v = p[j];
        if (v < 0 || v >= MAXN) bad = true;
    }
    bad = __syncthreads_or(bad);
    if (threadIdx.x == 0) g_is64 = bad ? 0 : 1;
}

__device__ __forceinline__ int edge_at(const void* ei, long long idx) {
    if (g_is64) return (int)((const long long*)ei)[idx];
    return ((const int*)ei)[idx];
}

// ---------------- preprocessing ----------------------------------------------
__global__ void k_init(int n) {
    int i = blockIdx.x * blockDim.x + threadIdx.x;
    if (i < n) { g_deg[i] = 1.0f; g_cnt[i] = 0; }   // 1.0 = self-loop weight
}

__global__ void k_deg(const void* __restrict__ ei,
                      const float* __restrict__ ea, int e) {
    int i = blockIdx.x * blockDim.x + threadIdx.x;
    if (i < e) {
        int dst = edge_at(ei, (long long)e + i);
        atomicAdd(&g_deg[dst], ea[i]);
        atomicAdd(&g_cnt[dst], 1);
    }
}

__global__ void k_dinv(int n) {
    int i = blockIdx.x * blockDim.x + threadIdx.x;
    if (i < n) g_dinv[i] = rsqrtf(g_deg[i]);
}

// Single-block exclusive scan of g_cnt -> g_offs / g_cursor (n <= 40960)
__global__ void k_scan(int n) {
    __shared__ int s[1024];
    int t = threadIdx.x;
    int ch = (n + 1023) >> 10;
    int base = t * ch;
    int sum = 0;
    for (int j = 0; j < ch; j++) {
        int idx = base + j;
        if (idx < n) sum += g_cnt[idx];
    }
    s[t] = sum;
    __syncthreads();
    // Kogge-Stone inclusive scan
    for (int off = 1; off < 1024; off <<= 1) {
        int v = (t >= off) ? s[t - off] : 0;
        __syncthreads();
        s[t] += v;
        __syncthreads();
    }
    if (t == 1023) g_offs[n] = s[1023];  // total == E
    int prefix = (t == 0) ? 0 : s[t - 1];
    for (int j = 0; j < ch; j++) {
        int idx = base + j;
        if (idx < n) {
            g_offs[idx]   = prefix;
            g_cursor[idx] = prefix;
            prefix += g_cnt[idx];
        }
    }
}

__global__ void k_fill(const void* __restrict__ ei,
                       const float* __restrict__ ea, int e) {
    int i = blockIdx.x * blockDim.x + threadIdx.x;
    if (i < e) {
        int src = edge_at(ei, i);
        int dst = edge_at(ei, (long long)e + i);
        int pos = atomicAdd(&g_cursor[dst], 1);
        g_srcs[pos] = src;
        g_nrm[pos]  = g_dinv[src] * ea[i] * g_dinv[dst];
    }
}

// ---------------- SGEMM: g_H[n,128] = A[n,128] @ W[128,128] ------------------
// 256 threads, 64x128 tile, BK=32, thread computes 4 rows x 8 cols.
// USE_G == 0: A = Ain (harness input x); USE_G == 1: A = g_G (layer-2 input).
template <int USE_G>
__global__ void k_gemm(const float* __restrict__ Ain, const float* __restrict__ W,
                       int nrows) {
    const float* __restrict__ A = USE_G ? (const float*)g_G : Ain;
    __shared__ float xs[64][33];   // +1 pad: conflict-free column reads
    __shared__ float ws[32][128];
    int tid = threadIdx.x;
    int tx = tid & 15;      // column group: cols tx + 16*nn
    int ty = tid >> 4;      // row group: rows ty*4 + m
    int row0 = blockIdx.x * 64;

    float acc[4][8];
#pragma unroll
    for (int m = 0; m < 4; m++)
#pragma unroll
        for (int nn = 0; nn < 8; nn++) acc[m][nn] = 0.0f;

    for (int k0 = 0; k0 < D; k0 += 32) {
        // load X tile: 64x32 = 512 float4, 2 per thread
#pragma unroll
        for (int j = 0; j < 2; j++) {
            int i = tid + j * 256;
            int r = i >> 3;
            int c4 = (i & 7) * 4;
            int row = row0 + r;
            if (row >= nrows) row = nrows - 1;
            float4 v = *(const float4*)&A[row * D + k0 + c4];
            xs[r][c4 + 0] = v.x; xs[r][c4 + 1] = v.y;
            xs[r][c4 + 2] = v.z; xs[r][c4 + 3] = v.w;
        }
        // load W tile: 32x128 = 1024 float4, 4 per thread
#pragma unroll
        for (int j = 0; j < 4; j++) {
            int i = tid + j * 256;
            int r = i >> 5;
            int c4 = (i & 31) * 4;
            *(float4*)&ws[r][c4] = *(const float4*)&W[(k0 + r) * D + c4];
        }
        __syncthreads();

#pragma unroll
        for (int kk = 0; kk < 32; kk++) {
            float rm[4], rn[8];
#pragma unroll
            for (int m = 0; m < 4; m++) rm[m] = xs[ty * 4 + m][kk];
#pragma unroll
            for (int nn = 0; nn < 8; nn++) rn[nn] = ws[kk][tx + nn * 16];
#pragma unroll
            for (int m = 0; m < 4; m++)
#pragma unroll
                for (int nn = 0; nn < 8; nn++)
                    acc[m][nn] += rm[m] * rn[nn];
        }
        __syncthreads();
    }

#pragma unroll
    for (int m = 0; m < 4; m++) {
        int row = row0 + ty * 4 + m;
        if (row < nrows) {
#pragma unroll
            for (int nn = 0; nn < 8; nn++)
                g_H[row * D + tx + nn * 16] = acc[m][nn];
        }
    }
}

// ---------------- aggregation: warp per node, float4 per lane ----------------
// out[n] = relu( sum_{e: dst=n} g_H[src_e]*norm_e + g_H[n]*dinv[n]^2 + bias )
// LN == 0: write to g_G.  LN == 1: LayerNorm with gamma/beta, write to outp.
template <int LN>
__global__ void k_agg(const float* __restrict__ bias,
                      const float* __restrict__ gamma, const float* __restrict__ beta,
                      float* __restrict__ outp, int n) {
    int w = (blockIdx.x * blockDim.x + threadIdx.x) >> 5;
    int lane = threadIdx.x & 31;
    if (w >= n) return;

    const float4* __restrict__ H4 = (const float4*)g_H;
    float di = g_dinv[w];
    float selfw = di * di;
    float4 h = H4[w * 32 + lane];
    float4 acc = make_float4(h.x * selfw, h.y * selfw, h.z * selfw, h.w * selfw);

    int ib = g_offs[w];
    int ie = g_offs[w + 1];
    int i = ib;
    for (; i + 2 <= ie; i += 2) {
        int   s0 = g_srcs[i],  s1 = g_srcs[i + 1];
        float w0 = g_nrm[i],   w1 = g_nrm[i + 1];
        float4 a = H4[s0 * 32 + lane];
        float4 b = H4[s1 * 32 + lane];
        acc.x += a.x * w0; acc.y += a.y * w0; acc.z += a.z * w0; acc.w += a.w * w0;
        acc.x += b.x * w1; acc.y += b.y * w1; acc.z += b.z * w1; acc.w += b.w * w1;
    }
    if (i < ie) {
        int s0 = g_srcs[i];
        float w0 = g_nrm[i];
        float4 a = H4[s0 * 32 + lane];
        acc.x += a.x * w0; acc.y += a.y * w0; acc.z += a.z * w0; acc.w += a.w * w0;
    }

    float4 b4 = ((const float4*)bias)[lane];
    acc.x = fmaxf(acc.x + b4.x, 0.0f);
    acc.y = fmaxf(acc.y + b4.y, 0.0f);
    acc.z = fmaxf(acc.z + b4.z, 0.0f);
    acc.w = fmaxf(acc.w + b4.w, 0.0f);

    if (LN) {
        float s1 = acc.x + acc.y + acc.z + acc.w;
#pragma unroll
        for (int o = 16; o > 0; o >>= 1)
            s1 += __shfl_xor_sync(0xffffffffu, s1, o);
        float mu = s1 * (1.0f / 128.0f);
        float dx = acc.x - mu, dy = acc.y - mu, dz = acc.z - mu, dw = acc.w - mu;
        float s2 = dx * dx + dy * dy + dz * dz + dw * dw;
#pragma unroll
        for (int o = 16; o > 0; o >>= 1)
            s2 += __shfl_xor_sync(0xffffffffu, s2, o);
        float r = rsqrtf(s2 * (1.0f / 128.0f) + 1e-5f);
        float4 g4  = ((const float4*)gamma)[lane];
        float4 be4 = ((const float4*)beta)[lane];
        acc.x = dx * r * g4.x + be4.x;
        acc.y = dy * r * g4.y + be4.y;
        acc.z = dz * r * g4.z + be4.z;
        acc.w = dw * r * g4.w + be4.w;
        ((float4*)outp)[w * 32 + lane] = acc;
    } else {
        ((float4*)g_G)[w * 32 + lane] = acc;
    }
}

// ---------------- launch ------------------------------------------------------
extern "C" void kernel_launch(void* const* d_in, const int* in_sizes, int n_in,
                              void* d_out, int out_size) {
    const float* x   = (const float*)d_in[0];
    const void*  ei  = d_in[1];
    const float* ea  = (const float*)d_in[2];
    const float* W1  = (const float*)d_in[3];
    const float* b1  = (const float*)d_in[4];
    const float* W2  = (const float*)d_in[5];
    const float* b2  = (const float*)d_in[6];
    const float* lng = (const float*)d_in[7];
    const float* lnb = (const float*)d_in[8];

    int n = in_sizes[0] / D;   // 40000
    int e = in_sizes[2];       // 640000

    int nb = (n + 255) / 256;
    int eb = (e + 255) / 256;

    // dtype probe + CSR + norm build (pure function of inputs every call)
    k_detect<<<1, 256>>>(ei);
    k_init<<<nb, 256>>>(n);
    k_deg<<<eb, 256>>>(ei, ea, e);
    k_dinv<<<nb, 256>>>(n);
    k_scan<<<1, 1024>>>(n);
    k_fill<<<eb, 256>>>(ei, ea, e);

    int gemm_blocks = (n + 63) / 64;
    int agg_blocks  = (n * 32 + 255) / 256;

    // layer 1: H = x @ W1 ; G = relu(agg(H) + b1)
    k_gemm<0><<<gemm_blocks, 256>>>(x, W1, n);
    k_agg<0><<<agg_blocks, 256>>>(b1, nullptr, nullptr, nullptr, n);
    // layer 2: H = G @ W2 ; out = LN(relu(agg(H) + b2))
    k_gemm<1><<<gemm_blocks, 256>>>(nullptr, W2, n);
    k_agg<1><<<agg_blocks, 256>>>(b2, lng, lnb, (float*)d_out, n);
}

// round 8
// speedup vs baseline: 1.0077x; 1.0077x over previous
#include <cuda_runtime.h>

#define D 128
#define MAXN 40000
#define MAXE 640000

// ---------------- scratch (static device globals; no allocation) -------------
__device__ float g_deg[MAXN];
__device__ int   g_cnt[MAXN];
__device__ int   g_offs[MAXN + 1];
__device__ int   g_cursor[MAXN];
__device__ int   g_srcs[MAXE];
__device__ float g_nrm[MAXE];
__device__ __align__(16) float g_H[MAXN * D];   // h = X @ W (current layer)
__device__ __align__(16) float g_G[MAXN * D];   // post-agg activations
__device__ int   g_is64;                        // edge_index dtype flag

// ---------------- f32x2 packed-FMA helpers ------------------------------------
__device__ __forceinline__ unsigned long long pack2(float lo, float hi) {
    unsigned long long d;
    asm("mov.b64 %0, {%1, %2};" : "=l"(d) : "f"(lo), "f"(hi));
    return d;
}
__device__ __forceinline__ void unpack2(unsigned long long v, float& lo, float& hi) {
    asm("mov.b64 {%0, %1}, %2;" : "=f"(lo), "=f"(hi) : "l"(v));
}
__device__ __forceinline__ unsigned long long fma2(unsigned long long a,
                                                   unsigned long long b,
                                                   unsigned long long c) {
    unsigned long long d;
    asm("fma.rn.f32x2 %0, %1, %2, %3;" : "=l"(d) : "l"(a), "l"(b), "l"(c));
    return d;
}

// ---------------- init + dtype probe ------------------------------------------
// Block 0 additionally probes edge_index dtype: the first 1024 values read as
// int64. int32 data reinterpreted as int64 merges random pairs -> >= 2^32 with
// overwhelming probability; all-in-range => true int64.
__global__ void k_init(const void* __restrict__ ei, int n) {
    int i = blockIdx.x * blockDim.x + threadIdx.x;
    if (i < n) { g_deg[i] = 1.0f; g_cnt[i] = 0; }   // 1.0 = self-loop weight
    if (blockIdx.x == 0) {
        const long long* p = (const long long*)ei;
        bool bad = false;
        for (int j = threadIdx.x; j < 1024; j += blockDim.x) {
            long long v = p[j];
            if (v < 0 || v >= MAXN) bad = true;
        }
        bad = __syncthreads_or(bad);
        if (threadIdx.x == 0) g_is64 = bad ? 0 : 1;
    }
}

__device__ __forceinline__ int edge_at(const void* ei, long long idx) {
    if (g_is64) return (int)((const long long*)ei)[idx];
    return ((const int*)ei)[idx];
}

__global__ void k_deg(const void* __restrict__ ei,
                      const float* __restrict__ ea, int e) {
    int i = blockIdx.x * blockDim.x + threadIdx.x;
    if (i < e) {
        int dst = edge_at(ei, (long long)e + i);
        atomicAdd(&g_deg[dst], ea[i]);
        atomicAdd(&g_cnt[dst], 1);
    }
}

// Single-block exclusive scan of g_cnt -> g_offs / g_cursor (n <= 40960)
__global__ void k_scan(int n) {
    __shared__ int s[1024];
    int t = threadIdx.x;
    int ch = (n + 1023) >> 10;
    int base = t * ch;
    int sum = 0;
    for (int j = 0; j < ch; j++) {
        int idx = base + j;
        if (idx < n) sum += g_cnt[idx];
    }
    s[t] = sum;
    __syncthreads();
    for (int off = 1; off < 1024; off <<= 1) {
        int v = (t >= off) ? s[t - off] : 0;
        __syncthreads();
        s[t] += v;
        __syncthreads();
    }
    if (t == 1023) g_offs[n] = s[1023];
    int prefix = (t == 0) ? 0 : s[t - 1];
    for (int j = 0; j < ch; j++) {
        int idx = base + j;
        if (idx < n) {
            g_offs[idx]   = prefix;
            g_cursor[idx] = prefix;
            prefix += g_cnt[idx];
        }
    }
}

__global__ void k_fill(const void* __restrict__ ei,
                       const float* __restrict__ ea, int e) {
    int i = blockIdx.x * blockDim.x + threadIdx.x;
    if (i < e) {
        int src = edge_at(ei, i);
        int dst = edge_at(ei, (long long)e + i);
        int pos = atomicAdd(&g_cursor[dst], 1);
        g_srcs[pos] = src;
        g_nrm[pos]  = rsqrtf(g_deg[src]) * ea[i] * rsqrtf(g_deg[dst]);
    }
}

// ---------------- SGEMM (f32x2): g_H[n,128] = A[n,128] @ W[128,128] ----------
// 256 threads, 128x128 tile, BK=16. Thread = 8 rows x 8 cols; rows packed in
// pairs into 64-bit regs -> fma.rn.f32x2 (2x FMA-pipe throughput vs FFMA).
// X tile stored k-major (xs_t[k][row], stride 130: even + conflict-free).
template <int USE_G>
__global__ void __launch_bounds__(256) k_gemm(const float* __restrict__ Ain,
                                              const float* __restrict__ W,
                                              int nrows) {
    const float* __restrict__ A = USE_G ? (const float*)g_G : Ain;
    __shared__ float xs_t[16][130];
    __shared__ float ws[16][128];
    int tid = threadIdx.x;
    int tx = tid & 15;      // cols tx*8 .. tx*8+7
    int ty = tid >> 4;      // rows ty*8 .. ty*8+7 (4 packed pairs)
    int row0 = blockIdx.x * 128;

    // global-load mapping for X: thread -> (row, 8-wide k segment)
    int lrow = tid >> 1;
    int lseg = (tid & 1) * 8;
    int grow = row0 + lrow;
    if (grow >= nrows) grow = nrows - 1;

    unsigned long long acc[4][8];
#pragma unroll
    for (int m = 0; m < 4; m++)
#pragma unroll
        for (int nn = 0; nn < 8; nn++) acc[m][nn] = 0ull;

    for (int k0 = 0; k0 < D; k0 += 16) {
        // X tile: 128 rows x 16 k, transposed into xs_t
        float4 va = *(const float4*)&A[grow * D + k0 + lseg];
        float4 vb = *(const float4*)&A[grow * D + k0 + lseg + 4];
        xs_t[lseg + 0][lrow] = va.x; xs_t[lseg + 1][lrow] = va.y;
        xs_t[lseg + 2][lrow] = va.z; xs_t[lseg + 3][lrow] = va.w;
        xs_t[lseg + 4][lrow] = vb.x; xs_t[lseg + 5][lrow] = vb.y;
        xs_t[lseg + 6][lrow] = vb.z; xs_t[lseg + 7][lrow] = vb.w;
        // W tile: 16 x 128 = 512 float4, 2 per thread
#pragma unroll
        for (int j = 0; j < 2; j++) {
            int i = tid + j * 256;
            int r = i >> 5;
            int c4 = (i & 31) * 4;
            *(float4*)&ws[r][c4] = *(const float4*)&W[(k0 + r) * D + c4];
        }
        __syncthreads();

#pragma unroll
        for (int kk = 0; kk < 16; kk++) {
            unsigned long long rm2[4];
#pragma unroll
            for (int m = 0; m < 4; m++)
                rm2[m] = *(const unsigned long long*)&xs_t[kk][ty * 8 + 2 * m];
            float4 fa = *(const float4*)&ws[kk][tx * 8];
            float4 fb = *(const float4*)&ws[kk][tx * 8 + 4];
            unsigned long long rnb[8];
            rnb[0] = pack2(fa.x, fa.x); rnb[1] = pack2(fa.y, fa.y);
            rnb[2] = pack2(fa.z, fa.z); rnb[3] = pack2(fa.w, fa.w);
            rnb[4] = pack2(fb.x, fb.x); rnb[5] = pack2(fb.y, fb.y);
            rnb[6] = pack2(fb.z, fb.z); rnb[7] = pack2(fb.w, fb.w);
#pragma unroll
            for (int m = 0; m < 4; m++)
#pragma unroll
                for (int nn = 0; nn < 8; nn++)
                    acc[m][nn] = fma2(rm2[m], rnb[nn], acc[m][nn]);
        }
        __syncthreads();
    }

    // epilogue: unpack row pairs, vector-store 2 float4 per row
#pragma unroll
    for (int m = 0; m < 4; m++) {
        float lo[8], hi[8];
#pragma unroll
        for (int nn = 0; nn < 8; nn++) unpack2(acc[m][nn], lo[nn], hi[nn]);
        int r_lo = row0 + ty * 8 + 2 * m;
        int r_hi = r_lo + 1;
        int c = tx * 8;
        if (r_lo < nrows) {
            *(float4*)&g_H[r_lo * D + c]     = make_float4(lo[0], lo[1], lo[2], lo[3]);
            *(float4*)&g_H[r_lo * D + c + 4] = make_float4(lo[4], lo[5], lo[6], lo[7]);
        }
        if (r_hi < nrows) {
            *(float4*)&g_H[r_hi * D + c]     = make_float4(hi[0], hi[1], hi[2], hi[3]);
            *(float4*)&g_H[r_hi * D + c + 4] = make_float4(hi[4], hi[5], hi[6], hi[7]);
        }
    }
}

// ---------------- aggregation: warp per node, float4 per lane ----------------
// out[n] = relu( sum_{e: dst=n} g_H[src_e]*nrm_e + g_H[n]/deg[n] + bias )
// LN == 0: write g_G.  LN == 1: LayerNorm with gamma/beta -> outp.
template <int LN>
__global__ void k_agg(const float* __restrict__ bias,
                      const float* __restrict__ gamma, const float* __restrict__ beta,
                      float* __restrict__ outp, int n) {
    int w = (blockIdx.x * blockDim.x + threadIdx.x) >> 5;
    int lane = threadIdx.x & 31;
    if (w >= n) return;

    const float4* __restrict__ H4 = (const float4*)g_H;
    float di = rsqrtf(g_deg[w]);
    float selfw = di * di;
    float4 h = __ldg(&H4[w * 32 + lane]);
    float4 acc = make_float4(h.x * selfw, h.y * selfw, h.z * selfw, h.w * selfw);

    int ib = g_offs[w];
    int ie = g_offs[w + 1];
    int i = ib;
    for (; i + 4 <= ie; i += 4) {
        int   s0 = g_srcs[i],     s1 = g_srcs[i + 1];
        int   s2 = g_srcs[i + 2], s3 = g_srcs[i + 3];
        float w0 = g_nrm[i],      w1 = g_nrm[i + 1];
        float w2 = g_nrm[i + 2],  w3 = g_nrm[i + 3];
        float4 a = __ldg(&H4[s0 * 32 + lane]);
        float4 b = __ldg(&H4[s1 * 32 + lane]);
        float4 c = __ldg(&H4[s2 * 32 + lane]);
        float4 d = __ldg(&H4[s3 * 32 + lane]);
        acc.x += a.x * w0; acc.y += a.y * w0; acc.z += a.z * w0; acc.w += a.w * w0;
        acc.x += b.x * w1; acc.y += b.y * w1; acc.z += b.z * w1; acc.w += b.w * w1;
        acc.x += c.x * w2; acc.y += c.y * w2; acc.z += c.z * w2; acc.w += c.w * w2;
        acc.x += d.x * w3; acc.y += d.y * w3; acc.z += d.z * w3; acc.w += d.w * w3;
    }
    for (; i < ie; i++) {
        int s0 = g_srcs[i];
        float w0 = g_nrm[i];
        float4 a = __ldg(&H4[s0 * 32 + lane]);
        acc.x += a.x * w0; acc.y += a.y * w0; acc.z += a.z * w0; acc.w += a.w * w0;
    }

    float4 b4 = ((const float4*)bias)[lane];
    acc.x = fmaxf(acc.x + b4.x, 0.0f);
    acc.y = fmaxf(acc.y + b4.y, 0.0f);
    acc.z = fmaxf(acc.z + b4.z, 0.0f);
    acc.w = fmaxf(acc.w + b4.w, 0.0f);

    if (LN) {
        float s1 = acc.x + acc.y + acc.z + acc.w;
#pragma unroll
        for (int o = 16; o > 0; o >>= 1)
            s1 += __shfl_xor_sync(0xffffffffu, s1, o);
        float mu = s1 * (1.0f / 128.0f);
        float dx = acc.x - mu, dy = acc.y - mu, dz = acc.z - mu, dw = acc.w - mu;
        float s2 = dx * dx + dy * dy + dz * dz + dw * dw;
#pragma unroll
        for (int o = 16; o > 0; o >>= 1)
            s2 += __shfl_xor_sync(0xffffffffu, s2, o);
        float r = rsqrtf(s2 * (1.0f / 128.0f) + 1e-5f);
        float4 g4  = ((const float4*)gamma)[lane];
        float4 be4 = ((const float4*)beta)[lane];
        acc.x = dx * r * g4.x + be4.x;
        acc.y = dy * r * g4.y + be4.y;
        acc.z = dz * r * g4.z + be4.z;
        acc.w = dw * r * g4.w + be4.w;
        ((float4*)outp)[w * 32 + lane] = acc;
    } else {
        ((float4*)g_G)[w * 32 + lane] = acc;
    }
}

// ---------------- launch ------------------------------------------------------
extern "C" void kernel_launch(void* const* d_in, const int* in_sizes, int n_in,
                              void* d_out, int out_size) {
    const float* x   = (const float*)d_in[0];
    const void*  ei  = d_in[1];
    const float* ea  = (const float*)d_in[2];
    const float* W1  = (const float*)d_in[3];
    const float* b1  = (const float*)d_in[4];
    const float* W2  = (const float*)d_in[5];
    const float* b2  = (const float*)d_in[6];
    const float* lng = (const float*)d_in[7];
    const float* lnb = (const float*)d_in[8];

    int n = in_sizes[0] / D;   // 40000
    int e = in_sizes[2];       // 640000

    int nb = (n + 255) / 256;
    int eb = (e + 255) / 256;

    // CSR + norm build (pure function of inputs every call)
    k_init<<<nb, 256>>>(ei, n);
    k_deg<<<eb, 256>>>(ei, ea, e);
    k_scan<<<1, 1024>>>(n);
    k_fill<<<eb, 256>>>(ei, ea, e);

    int gemm_blocks = (n + 127) / 128;
    int agg_blocks  = (n * 32 + 255) / 256;

    // layer 1: H = x @ W1 ; G = relu(agg(H) + b1)
    k_gemm<0><<<gemm_blocks, 256>>>(x, W1, n);
    k_agg<0><<<agg_blocks, 256>>>(b1, nullptr, nullptr, nullptr, n);
    // layer 2: H = G @ W2 ; out = LN(relu(agg(H) + b2))
    k_gemm<1><<<gemm_blocks, 256>>>(nullptr, W2, n);
    k_agg<1><<<agg_blocks, 256>>>(b2, lng, lnb, (float*)d_out, n);
}